// round 4
// baseline (speedup 1.0000x reference)
#include <cuda_runtime.h>
#include <cuda_bf16.h>
#include <math_constants.h>
#include <cstdint>

// Problem constants
#define BATCH 2
#define SEQ   2048
#define CH    1024
#define HEADS 16
#define DH    64
#define MROWS (BATCH*SEQ)   // 4096

// ---------------------------------------------------------------------------
// Device scratch
// ---------------------------------------------------------------------------
__device__ float g_qkv[(size_t)MROWS * 3 * CH];
__device__ float g_att[(size_t)MROWS * CH];
__device__ __nv_bfloat16 g_Ahi[(size_t)MROWS * CH];
__device__ __nv_bfloat16 g_Alo[(size_t)MROWS * CH];
__device__ __nv_bfloat16 g_BQhi[(size_t)(3*CH) * CH];
__device__ __nv_bfloat16 g_BQlo[(size_t)(3*CH) * CH];
__device__ __nv_bfloat16 g_BPhi[(size_t)CH * CH];
__device__ __nv_bfloat16 g_BPlo[(size_t)CH * CH];

// ---------------------------------------------------------------------------
// Helpers
// ---------------------------------------------------------------------------
__device__ __forceinline__ uint32_t smem_u32(const void* p) {
    uint32_t a;
    asm("{ .reg .u64 t; cvta.to.shared.u64 t, %1; cvt.u32.u64 %0, t; }"
        : "=r"(a) : "l"(p));
    return a;
}

#define SWZ128(o) ((o) ^ (((o) >> 3) & 0x70))

#define CP_ASYNC16(dst_u32, src_ptr) \
    asm volatile("cp.async.cg.shared.global [%0], [%1], 16;\n" \
                 :: "r"(dst_u32), "l"(src_ptr))
#define CP_COMMIT() asm volatile("cp.async.commit_group;\n" ::: "memory")
#define CP_WAIT0()  asm volatile("cp.async.wait_group 0;\n" ::: "memory")
#define CP_WAIT1()  asm volatile("cp.async.wait_group 1;\n" ::: "memory")

#define LDSM_X4(r0, r1, r2, r3, addr) \
    asm volatile("ldmatrix.sync.aligned.m8n8.x4.shared.b16 {%0,%1,%2,%3}, [%4];" \
                 : "=r"(r0), "=r"(r1), "=r"(r2), "=r"(r3) : "r"(addr))
#define LDSM_X2(r0, r1, addr) \
    asm volatile("ldmatrix.sync.aligned.m8n8.x2.shared.b16 {%0,%1}, [%2];" \
                 : "=r"(r0), "=r"(r1) : "r"(addr))
#define MMA16816(d, a0, a1, a2, a3, b0, b1) \
    asm volatile("mma.sync.aligned.m16n8k16.row.col.f32.bf16.bf16.f32 " \
                 "{%0,%1,%2,%3},{%4,%5,%6,%7},{%8,%9},{%0,%1,%2,%3};" \
                 : "+f"((d)[0]), "+f"((d)[1]), "+f"((d)[2]), "+f"((d)[3]) \
                 : "r"(a0), "r"(a1), "r"(a2), "r"(a3), "r"(b0), "r"(b1))

// ---------------------------------------------------------------------------
// bf16x3 GEMM: C[M,N] = (Ahi+Alo)[M,K] @ (Bhi+Blo)[N,K]^T + bias
// CTA tile 256x128, KC=64, 2-stage cp.async double buffer.
// 8 warps in 4(M) x 2(N) grid, 64x64 warp tiles, m16n8k16 bf16 MMA.
// Stage layout: Ahi 32KB | Alo 32KB | Bhi 16KB | Blo 16KB  (96KB/stage)
// ---------------------------------------------------------------------------
#define KC 64
#define STAGE_BYTES 98304
#define GEMM_SMEM (1024 + 2 * STAGE_BYTES)   // 197632 B

__device__ __forceinline__ void load_chunk_tiles(
    const __nv_bfloat16* __restrict__ Ah, const __nv_bfloat16* __restrict__ Al,
    const __nv_bfloat16* __restrict__ Bh, const __nv_bfloat16* __restrict__ Bl,
    int K, int m0, int n0, int c, uint32_t st, int tid)
{
    // A: 256 rows x 8 cols of 16B -> 2048 slots, 8 per thread (hi+lo)
    #pragma unroll
    for (int t = 0; t < 8; t++) {
        int idx = t * 256 + tid;
        int row = idx >> 3;
        int col = idx & 7;
        uint32_t off = SWZ128((uint32_t)(row * 128 + col * 16));
        size_t ga = (size_t)(m0 + row) * K + c * KC + col * 8;
        CP_ASYNC16(st + off,         Ah + ga);
        CP_ASYNC16(st + 32768 + off, Al + ga);
    }
    // B: 128 rows x 8 cols of 16B -> 1024 slots, 4 per thread (hi+lo)
    #pragma unroll
    for (int t = 0; t < 4; t++) {
        int idx = t * 256 + tid;
        int row = idx >> 3;
        int col = idx & 7;
        uint32_t off = SWZ128((uint32_t)(row * 128 + col * 16));
        size_t gb = (size_t)(n0 + row) * K + c * KC + col * 8;
        CP_ASYNC16(st + 65536 + off, Bh + gb);
        CP_ASYNC16(st + 81920 + off, Bl + gb);
    }
}

__global__ __launch_bounds__(256, 1)
void gemm_bf16x3_kernel(const __nv_bfloat16* __restrict__ Ah,
                        const __nv_bfloat16* __restrict__ Al,
                        const __nv_bfloat16* __restrict__ Bh,
                        const __nv_bfloat16* __restrict__ Bl,
                        const float* __restrict__ bias,
                        float* __restrict__ C,
                        int N, int K)
{
    extern __shared__ char smem[];
    const uint32_t sb = smem_u32(smem);
    const uint32_t tiles = (sb + 1023) & ~1023u;
    const int tid  = threadIdx.x;
    const int wid  = tid >> 5;
    const int lane = tid & 31;
    const int m0 = blockIdx.y * 256;
    const int n0 = blockIdx.x * 128;
    const int NCHUNK = K / KC;

    const int warpM = wid >> 1;    // 0..3 -> 64-row band
    const int warpN = wid & 1;     // 0..1 -> 64-col band

    float acc[4][8][4];
    #pragma unroll
    for (int mt = 0; mt < 4; mt++)
        #pragma unroll
        for (int nt = 0; nt < 8; nt++)
            #pragma unroll
            for (int e = 0; e < 4; e++) acc[mt][nt][e] = 0.0f;

    // per-lane ldmatrix address components
    const int aRowSel  = warpM * 64 + (lane & 15);
    const int aByteSel = (lane >> 4) * 16;
    const int bRowSel  = warpN * 64 + (lane & 7);
    const int bByteSel = ((lane >> 3) & 1) * 16;

    load_chunk_tiles(Ah, Al, Bh, Bl, K, m0, n0, 0, tiles, tid);
    CP_COMMIT();

    for (int c = 0; c < NCHUNK; ++c) {
        if (c + 1 < NCHUNK) {
            load_chunk_tiles(Ah, Al, Bh, Bl, K, m0, n0, c + 1,
                             tiles + ((c + 1) & 1) * STAGE_BYTES, tid);
            CP_COMMIT();
            CP_WAIT1();
        } else {
            CP_WAIT0();
        }
        __syncthreads();

        const uint32_t st = tiles + (c & 1) * STAGE_BYTES;

        #pragma unroll
        for (int kk = 0; kk < 4; kk++) {
            // A fragments for this kk (hi + lo), reused across all nt
            uint32_t ah[4][4], al[4][4];
            #pragma unroll
            for (int mt = 0; mt < 4; mt++) {
                uint32_t aoff = SWZ128((uint32_t)((aRowSel + mt * 16) * 128 + kk * 32 + aByteSel));
                LDSM_X4(ah[mt][0], ah[mt][1], ah[mt][2], ah[mt][3], st + aoff);
                LDSM_X4(al[mt][0], al[mt][1], al[mt][2], al[mt][3], st + 32768 + aoff);
            }
            #pragma unroll
            for (int nt = 0; nt < 8; nt++) {
                uint32_t boff = SWZ128((uint32_t)((bRowSel + nt * 8) * 128 + kk * 32 + bByteSel));
                uint32_t bh0, bh1, bl0, bl1;
                LDSM_X2(bh0, bh1, st + 65536 + boff);
                LDSM_X2(bl0, bl1, st + 81920 + boff);
                // dependent MMAs to the same acc are 4 apart
                #pragma unroll
                for (int mt = 0; mt < 4; mt++)
                    MMA16816(acc[mt][nt], ah[mt][0], ah[mt][1], ah[mt][2], ah[mt][3], bh0, bh1);
                #pragma unroll
                for (int mt = 0; mt < 4; mt++)
                    MMA16816(acc[mt][nt], al[mt][0], al[mt][1], al[mt][2], al[mt][3], bh0, bh1);
                #pragma unroll
                for (int mt = 0; mt < 4; mt++)
                    MMA16816(acc[mt][nt], ah[mt][0], ah[mt][1], ah[mt][2], ah[mt][3], bl0, bl1);
            }
        }
        __syncthreads();
    }

    // epilogue: bias + store
    #pragma unroll
    for (int mt = 0; mt < 4; mt++) {
        int r0 = m0 + warpM * 64 + mt * 16 + (lane >> 2);
        #pragma unroll
        for (int nt = 0; nt < 8; nt++) {
            int c0 = n0 + warpN * 64 + nt * 8 + (lane & 3) * 2;
            float2 bv = *(const float2*)(bias + c0);
            float2 o0 = make_float2(acc[mt][nt][0] + bv.x, acc[mt][nt][1] + bv.y);
            float2 o1 = make_float2(acc[mt][nt][2] + bv.x, acc[mt][nt][3] + bv.y);
            *(float2*)(C + (size_t)r0 * N + c0)       = o0;
            *(float2*)(C + (size_t)(r0 + 8) * N + c0) = o1;
        }
    }
}

// ---------------------------------------------------------------------------
// Split fp32 -> bf16 hi + bf16 residual lo
// ---------------------------------------------------------------------------
__global__ __launch_bounds__(256)
void conv_split_kernel(const float* __restrict__ in,
                       __nv_bfloat16* __restrict__ hi,
                       __nv_bfloat16* __restrict__ lo, int n4)
{
    int i = blockIdx.x * 256 + threadIdx.x;
    if (i >= n4) return;
    float4 v = ((const float4*)in)[i];
    __nv_bfloat16 h0 = __float2bfloat16(v.x);
    __nv_bfloat16 h1 = __float2bfloat16(v.y);
    __nv_bfloat16 h2 = __float2bfloat16(v.z);
    __nv_bfloat16 h3 = __float2bfloat16(v.w);
    __nv_bfloat16 l0 = __float2bfloat16(v.x - __bfloat162float(h0));
    __nv_bfloat16 l1 = __float2bfloat16(v.y - __bfloat162float(h1));
    __nv_bfloat16 l2 = __float2bfloat16(v.z - __bfloat162float(h2));
    __nv_bfloat16 l3 = __float2bfloat16(v.w - __bfloat162float(h3));
    ((__nv_bfloat162*)hi)[2 * i + 0] = __nv_bfloat162(h0, h1);
    ((__nv_bfloat162*)hi)[2 * i + 1] = __nv_bfloat162(h2, h3);
    ((__nv_bfloat162*)lo)[2 * i + 0] = __nv_bfloat162(l0, l1);
    ((__nv_bfloat162*)lo)[2 * i + 1] = __nv_bfloat162(l2, l3);
}

// ---------------------------------------------------------------------------
// Transpose + split: W[K,N] fp32 -> Wt hi/lo [N,K] bf16
// ---------------------------------------------------------------------------
__global__ __launch_bounds__(256)
void conv_transpose_kernel(const float* __restrict__ W,
                           __nv_bfloat16* __restrict__ hi,
                           __nv_bfloat16* __restrict__ lo, int K, int N)
{
    __shared__ float tile[32][33];
    const int n0 = blockIdx.x * 32;
    const int k0 = blockIdx.y * 32;
    const int tx = threadIdx.x & 31;
    const int ty = threadIdx.x >> 5;

    #pragma unroll
    for (int j = ty; j < 32; j += 8)
        tile[j][tx] = W[(size_t)(k0 + j) * N + n0 + tx];
    __syncthreads();

    #pragma unroll
    for (int j = ty; j < 32; j += 8) {
        float v = tile[tx][j];
        __nv_bfloat16 h = __float2bfloat16(v);
        __nv_bfloat16 l = __float2bfloat16(v - __bfloat162float(h));
        size_t o = (size_t)(n0 + j) * K + k0 + tx;
        hi[o] = h;
        lo[o] = l;
    }
}

// ---------------------------------------------------------------------------
// Fenwick sparse attention: <=12 keys per query, one warp per (b,h,t)
// ---------------------------------------------------------------------------
__global__ __launch_bounds__(256)
void fenwick_attn_kernel(const float* __restrict__ qkv, float* __restrict__ out)
{
    const int warp = threadIdx.x >> 5;
    const int lane = threadIdx.x & 31;
    const int t  = blockIdx.x * 8 + warp;
    const int bh = blockIdx.y;
    const int b = bh >> 4;
    const int h = bh & 15;

    const float scale = 0.125f;
    const size_t rowStride = 3 * CH;
    const float* base = qkv + (size_t)b * SEQ * rowStride;

    const float* qp = base + (size_t)t * rowStride + h * DH;
    const float q0 = qp[lane];
    const float q1 = qp[lane + 32];

    int pos[12];
    int np = 0;
    pos[np++] = t;
    for (int step = 1; t - step >= 0; step <<= 1) pos[np++] = t - step;

    float s[12];
    float m = -CUDART_INF_F;
    for (int i = 0; i < np; i++) {
        const float* kp = base + (size_t)pos[i] * rowStride + CH + h * DH;
        float d = q0 * kp[lane] + q1 * kp[lane + 32];
        #pragma unroll
        for (int off = 16; off; off >>= 1) d += __shfl_xor_sync(0xFFFFFFFFu, d, off);
        d *= scale;
        s[i] = d;
        m = fmaxf(m, d);
    }

    float denom = 0.0f;
    for (int i = 0; i < np; i++) { s[i] = __expf(s[i] - m); denom += s[i]; }
    const float inv = 1.0f / denom;

    float o0 = 0.0f, o1 = 0.0f;
    for (int i = 0; i < np; i++) {
        const float* vp = base + (size_t)pos[i] * rowStride + 2 * CH + h * DH;
        o0 = fmaf(s[i], vp[lane], o0);
        o1 = fmaf(s[i], vp[lane + 32], o1);
    }

    float* op = out + ((size_t)b * SEQ + t) * CH + h * DH;
    op[lane]      = o0 * inv;
    op[lane + 32] = o1 * inv;
}

// ---------------------------------------------------------------------------
// Launch
// ---------------------------------------------------------------------------
extern "C" void kernel_launch(void* const* d_in, const int* in_sizes, int n_in,
                              void* d_out, int out_size)
{
    const float* x      = (const float*)d_in[0];
    const float* W_qkv  = (const float*)d_in[1];
    const float* b_qkv  = (const float*)d_in[2];
    const float* W_proj = (const float*)d_in[3];
    const float* b_proj = (const float*)d_in[4];
    float* out = (float*)d_out;

    float *qkv, *att;
    __nv_bfloat16 *Ahi, *Alo, *BQhi, *BQlo, *BPhi, *BPlo;
    cudaGetSymbolAddress((void**)&qkv,  g_qkv);
    cudaGetSymbolAddress((void**)&att,  g_att);
    cudaGetSymbolAddress((void**)&Ahi,  g_Ahi);
    cudaGetSymbolAddress((void**)&Alo,  g_Alo);
    cudaGetSymbolAddress((void**)&BQhi, g_BQhi);
    cudaGetSymbolAddress((void**)&BQlo, g_BQlo);
    cudaGetSymbolAddress((void**)&BPhi, g_BPhi);
    cudaGetSymbolAddress((void**)&BPlo, g_BPlo);

    cudaFuncSetAttribute(gemm_bf16x3_kernel,
                         cudaFuncAttributeMaxDynamicSharedMemorySize, GEMM_SMEM);

    conv_transpose_kernel<<<dim3(3 * CH / 32, CH / 32), 256>>>(W_qkv, BQhi, BQlo, CH, 3 * CH);
    conv_transpose_kernel<<<dim3(CH / 32, CH / 32), 256>>>(W_proj, BPhi, BPlo, CH, CH);
    conv_split_kernel<<<(MROWS * CH / 4 + 255) / 256, 256>>>(x, Ahi, Alo, MROWS * CH / 4);

    // GEMM1: [4096, 3072] = x @ W_qkv + b_qkv   (CTA 256x128 grid 24x16)
    gemm_bf16x3_kernel<<<dim3(3 * CH / 128, MROWS / 256), 256, GEMM_SMEM>>>(
        Ahi, Alo, BQhi, BQlo, b_qkv, qkv, 3 * CH, CH);

    fenwick_attn_kernel<<<dim3(SEQ / 8, BATCH * HEADS), 256>>>(qkv, att);

    conv_split_kernel<<<(MROWS * CH / 4 + 255) / 256, 256>>>(att, Ahi, Alo, MROWS * CH / 4);

    // GEMM2: [4096, 1024] = att @ W_proj + b_proj  (grid 8x16)
    gemm_bf16x3_kernel<<<dim3(CH / 128, MROWS / 256), 256, GEMM_SMEM>>>(
        Ahi, Alo, BPhi, BPlo, b_proj, out, CH, CH);
}